// round 12
// baseline (speedup 1.0000x reference)
#include <cuda_runtime.h>
#include <cuda_bf16.h>

// VanillaRNN diagonal recurrence, f32. R11 post-mortem: single wave, duration
// set by FMA-role warps' serial chain at ~6.3 cyc per DEPENDENT instruction
// (lat 4 + arbitration ~2.3 under 14-warp SMSP load); R11's 26-serial-op
// tanh_fma -> 165 cyc/step -> 169K cyc. v2 designs to that model:
//  - lean tanh_fma with ~16 serial ops (deg5 Estrin exp2, deg3 Chebyshev
//    recip seed + 1 Newton) -> ~100 cyc/step
//  - 3-of-7 blocks' warps 4..7 are FMA-role (3 FMA + 11 MUFU warps/SMSP)
//  - FMA warps hand every 8th step back to MUFU (x=1/8)
//  balance: MUFU port 8*(11+3/8)*1024 ~ 93K  ==  FMA chain (7/8*100+1/8*30)*1024 ~ 93K
// f16 state fatal (R4); all state f32.

#define RB 1024
#define RT 1024
#define RH 256
#define RC 10

__device__ __forceinline__ float tanh_hw(float x) {
    float r;
    asm("tanh.approx.f32 %0, %1;" : "=f"(r) : "f"(x));
    return r;
}

// Lean all-FMA tanh, ~16 serial ops, |err| ~4e-6 abs.
// tanh(z)=sign(z)*(1-2e*y), e=2^(-2|z|/ln2), y ~= 1/(1+e).
__device__ __forceinline__ float tanh_fma(float z) {
    const float NL2E2 = -2.885390081777927f;   // -2/ln2
    const float MAGIC = 12582912.0f;           // 1.5*2^23
    float az = fminf(fabsf(z), 20.0f);
    float t  = fmaf(az, NL2E2, MAGIC);
    float kf = t - MAGIC;
    float r  = fmaf(az, NL2E2, -kf);           // r in [-0.5,0.5]
    float sc = __int_as_float((__float_as_int(t) + (127 - 0x4B400000)) << 23); // 2^k
    // 2^r Taylor deg-5, Estrin (rel err < 3e-7)
    float r2 = r * r;
    float r4 = r2 * r2;
    float q0 = fmaf(0.6931471806f,  r, 1.0f);
    float q1 = fmaf(0.0555041087f,  r, 0.2402265070f);
    float q2 = fmaf(0.0013333558f,  r, 0.0096181291f);
    float p  = fmaf(r2, q1, q0);
    p = fmaf(r4, q2, p);
    float e  = p * sc;                         // e^{-2|z|} in (0,1]
    float den = e + 1.0f;
    // 1/(1+e): deg-3 Chebyshev seed on e in [0,1] (rel ~1.2e-3) + 1 Newton -> ~2e-6
    float e2 = e * e;
    float s0 = fmaf(-0.946906f, e, 0.998523f);
    float s1 = fmaf(-0.228585f, e, 0.675919f);
    float y  = fmaf(s1, e2, s0);
    float w  = fmaf(-den, y, 2.0f);
    y = y * w;
    float e2m = e + e;                         // parallel slot
    float res = fmaf(-e2m, y, 1.0f);
    return copysignf(res, z);
}

__global__ __launch_bounds__(RH, 7)
void vanilla_rnn_kernel(const float* __restrict__ x,
                        const float* __restrict__ W_hx,
                        const float* __restrict__ W_hh,
                        const float* __restrict__ b_h,
                        const float* __restrict__ W_hp,
                        const float* __restrict__ b_o,
                        float* __restrict__ out)
{
    __shared__ float4 xs4[RT / 4];
    __shared__ float  hs[RH];

    const int b = blockIdx.x;
    const int h = threadIdx.x;

    {
        const float4* xrow = reinterpret_cast<const float4*>(x + (size_t)b * RT);
        xs4[h] = xrow[h];
    }

    const float wi = W_hx[h];
    const float wd = W_hh[h * RH + h];
    const float bh = b_h[h];

    __syncthreads();

    // FMA role: in 3 of every 7 co-resident blocks (148 == 1 mod 7 covers all
    // residues per SM), warps 4..7 -> exactly 3 FMA warps per SMSP chip-wide.
    const bool fma_role = ((b % 7) < 3) && (h >= 128);

    float hv = 0.0f;
    if (fma_role) {
        // 128 chunks x 8 steps: 7 FMA-pipe tanh + 1 MUFU tanh (x = 1/8).
        #pragma unroll 2
        for (int c = 0; c < 128; c++) {
            const int q = c * 2;
            float4 xa = xs4[q + 0];
            float4 xb = xs4[q + 1];
            float a0 = fmaf(xa.x, wi, bh), a1 = fmaf(xa.y, wi, bh);
            float a2 = fmaf(xa.z, wi, bh), a3 = fmaf(xa.w, wi, bh);
            float a4 = fmaf(xb.x, wi, bh), a5 = fmaf(xb.y, wi, bh);
            float a6 = fmaf(xb.z, wi, bh), a7 = fmaf(xb.w, wi, bh);
            hv = tanh_fma(fmaf(hv, wd, a0));
            hv = tanh_fma(fmaf(hv, wd, a1));
            hv = tanh_fma(fmaf(hv, wd, a2));
            hv = tanh_fma(fmaf(hv, wd, a3));
            hv = tanh_fma(fmaf(hv, wd, a4));
            hv = tanh_fma(fmaf(hv, wd, a5));
            hv = tanh_fma(fmaf(hv, wd, a6));
            hv = tanh_hw (fmaf(hv, wd, a7));   // MUFU assist
        }
    } else {
        #pragma unroll 4
        for (int q = 0; q < RT / 4; q++) {
            float4 xv = xs4[q];
            float a0 = fmaf(xv.x, wi, bh);
            float a1 = fmaf(xv.y, wi, bh);
            float a2 = fmaf(xv.z, wi, bh);
            float a3 = fmaf(xv.w, wi, bh);
            hv = tanh_hw(fmaf(hv, wd, a0));
            hv = tanh_hw(fmaf(hv, wd, a1));
            hv = tanh_hw(fmaf(hv, wd, a2));
            hv = tanh_hw(fmaf(hv, wd, a3));
        }
    }

    hs[h] = hv;
    __syncthreads();

    if (h < RC) {
        const float* wrow = W_hp + h * RH;
        float acc = b_o[h];
        #pragma unroll 8
        for (int j = 0; j < RH; j++)
            acc = fmaf(hs[j], wrow[j], acc);
        out[b * RC + h] = acc;
    }
}

extern "C" void kernel_launch(void* const* d_in, const int* in_sizes, int n_in,
                              void* d_out, int out_size)
{
    const float* x    = (const float*)d_in[0];
    const float* W_hx = (const float*)d_in[1];
    const float* W_hh = (const float*)d_in[2];
    const float* b_h  = (const float*)d_in[3];
    const float* W_hp = (const float*)d_in[4];
    const float* b_o  = (const float*)d_in[5];
    float* out = (float*)d_out;

    vanilla_rnn_kernel<<<RB, RH>>>(x, W_hx, W_hh, b_h, W_hp, b_o, out);
}

// round 15
// speedup vs baseline: 1.7480x; 1.7480x over previous
#include <cuda_runtime.h>
#include <cuda_bf16.h>

// VanillaRNN diagonal recurrence, f32, pure-MUFU core (R5 shape — proven at
// the dual ceiling max(MUFU port 114.7K, issue structure ~119K cyc/SMSP)).
// Closed lines: FMA offload (R6/7/8/11/12), f16 anything (R4/R13), ILP/grid
// reshape (R3/R9). This round trims the measurable residue: the serial
// 10-thread epilogue tail (~1.5K cyc/block) -> 160-thread parallel dot.

#define RB 1024
#define RT 1024
#define RH 256
#define RC 10

__device__ __forceinline__ float tanh_hw(float x) {
    float r;
    asm("tanh.approx.f32 %0, %1;" : "=f"(r) : "f"(x));
    return r;
}

__global__ __launch_bounds__(RH, 8)
void vanilla_rnn_kernel(const float* __restrict__ x,
                        const float* __restrict__ W_hx,
                        const float* __restrict__ W_hh,
                        const float* __restrict__ b_h,
                        const float* __restrict__ W_hp,
                        const float* __restrict__ b_o,
                        float* __restrict__ out)
{
    __shared__ float4 xs4[RT / 4];       // this block's x row (4 KB)
    __shared__ float  hs[RH];            // final hidden state
    __shared__ float  psum[RC][16];      // epilogue partials

    const int b = blockIdx.x;
    const int h = threadIdx.x;

    {
        const float4* xrow = reinterpret_cast<const float4*>(x + (size_t)b * RT);
        xs4[h] = xrow[h];
    }

    const float wi = W_hx[h];
    const float wd = W_hh[h * RH + h];
    const float bh = b_h[h];

    __syncthreads();

    float hv = 0.0f;
    // 16 steps per iteration: 4 LDS.128, a_t computed off the carried chain.
    #pragma unroll 1
    for (int c = 0; c < RT / 16; c++) {
        const int q = c * 4;
        #pragma unroll
        for (int s = 0; s < 4; s++) {
            float4 xv = xs4[q + s];
            float a0 = fmaf(xv.x, wi, bh);
            float a1 = fmaf(xv.y, wi, bh);
            float a2 = fmaf(xv.z, wi, bh);
            float a3 = fmaf(xv.w, wi, bh);
            hv = tanh_hw(fmaf(hv, wd, a0));
            hv = tanh_hw(fmaf(hv, wd, a1));
            hv = tanh_hw(fmaf(hv, wd, a2));
            hv = tanh_hw(fmaf(hv, wd, a3));
        }
    }

    hs[h] = hv;
    __syncthreads();

    // Parallel epilogue: 160 threads, each a 16-wide partial dot.
    // thread (c, seg): c = h/16 in [0,10), seg = h%16.
    if (h < RC * 16) {
        const int c   = h >> 4;
        const int seg = h & 15;
        const float* wrow = W_hp + c * RH + seg * 16;
        const float* hrow = hs + seg * 16;
        float acc = 0.0f;
        #pragma unroll
        for (int j = 0; j < 16; j++)
            acc = fmaf(hrow[j], wrow[j], acc);
        psum[c][seg] = acc;
    }
    __syncthreads();

    if (h < RC) {
        float acc = b_o[h];
        #pragma unroll
        for (int s = 0; s < 16; s++)
            acc += psum[h][s];
        out[b * RC + h] = acc;
    }
}

extern "C" void kernel_launch(void* const* d_in, const int* in_sizes, int n_in,
                              void* d_out, int out_size)
{
    const float* x    = (const float*)d_in[0];
    const float* W_hx = (const float*)d_in[1];
    const float* W_hh = (const float*)d_in[2];
    const float* b_h  = (const float*)d_in[3];
    const float* W_hp = (const float*)d_in[4];
    const float* b_o  = (const float*)d_in[5];
    float* out = (float*)d_out;

    vanilla_rnn_kernel<<<RB, RH>>>(x, W_hx, W_hh, b_h, W_hp, b_o, out);
}

// round 16
// speedup vs baseline: 1.7670x; 1.0109x over previous
#include <cuda_runtime.h>
#include <cuda_bf16.h>

// VanillaRNN diagonal recurrence, f32 — converged configuration.
// Session model: MUFU-port-bound; floor = 14 warps/SMSP x 1024 x rt8 =
// 114.7K cyc (~63.5us); this kernel runs ~118K. Closed lines (measured):
// FMA offload beyond beta~0.1 (serial-chain arbitration), f16 anywhere
// (error amplification 40-80x vs 1e-3 gate), ILP/grid reshaping (chain-count
// neutral or quantization-worse). beta=0.1 MUFU->FMA interleave retained
// (best empirical: 67.84us bench in R7).

#define RB 1024
#define RT 1024
#define RH 256
#define RC 10

__device__ __forceinline__ float tanh_hw(float x) {
    float r;
    asm("tanh.approx.f32 %0, %1;" : "=f"(r) : "f"(x));
    return r;
}

// Lean all-FMA/ALU tanh (R7-validated): ~15 FMA + 4 ALU ops, |err| ~4e-5 abs.
__device__ __forceinline__ float tanh_fma(float z) {
    const float NL2E2 = -2.885390081777927f;   // -2/ln2
    const float MAGIC = 12582912.0f;           // 1.5 * 2^23
    float az = fminf(fabsf(z), 40.0f);
    float t  = fmaf(az, NL2E2, MAGIC);
    float kf = t - MAGIC;
    float r  = fmaf(az, NL2E2, -kf);
    float sc = __int_as_float((__float_as_int(t) + (127 - 0x4B400000)) << 23);
    float r2 = r * r;
    float q0 = fmaf(0.6931471806f, r, 1.0f);
    float q1 = fmaf(0.0555041087f, r, 0.2402265070f);
    float qq = fmaf(0.0096181291f, r2, q1);
    float p  = fmaf(qq, r2, q0);
    float e  = p * sc;
    float den = e + 1.0f;
    float y  = fmaf(den, -0.5f, 1.45710678f);
    y = y * fmaf(-den, y, 2.0f);
    y = y * fmaf(-den, y, 2.0f);
    float e2 = e + e;
    float res = fmaf(-e2, y, 1.0f);
    return copysignf(res, z);
}

__global__ __launch_bounds__(RH, 7)
void vanilla_rnn_kernel(const float* __restrict__ x,
                        const float* __restrict__ W_hx,
                        const float* __restrict__ W_hh,
                        const float* __restrict__ b_h,
                        const float* __restrict__ W_hp,
                        const float* __restrict__ b_o,
                        float* __restrict__ out)
{
    __shared__ float4 xs4[RT / 4];   // this block's x row (4 KB)
    __shared__ float  hs[RH];        // final hidden state
    __shared__ float  psum[RC][16];  // epilogue partials

    const int b = blockIdx.x;
    const int h = threadIdx.x;

    {
        const float4* xrow = reinterpret_cast<const float4*>(x + (size_t)b * RT);
        xs4[h] = xrow[h];
    }

    const float wi = W_hx[h];
    const float wd = W_hh[h * RH + h];
    const float bh = b_h[h];

    __syncthreads();

    float hv = 0.0f;
    // 51 chunks x 20 steps (5 float4 loads); steps 11 and 19 of each chunk on
    // the FMA pipe (beta = 0.1, uniform per SMSP). Tail 4 steps on MUFU.
    #pragma unroll 1
    for (int c = 0; c < 51; c++) {
        const int q = c * 5;
        #pragma unroll
        for (int s = 0; s < 5; s++) {
            float4 xv = xs4[q + s];
            float a0 = fmaf(xv.x, wi, bh);
            float a1 = fmaf(xv.y, wi, bh);
            float a2 = fmaf(xv.z, wi, bh);
            float a3 = fmaf(xv.w, wi, bh);
            hv = tanh_hw(fmaf(hv, wd, a0));
            hv = tanh_hw(fmaf(hv, wd, a1));
            hv = tanh_hw(fmaf(hv, wd, a2));
            if (s == 2 || s == 4)
                hv = tanh_fma(fmaf(hv, wd, a3));
            else
                hv = tanh_hw (fmaf(hv, wd, a3));
        }
    }
    {
        float4 xv = xs4[255];
        hv = tanh_hw(fmaf(hv, wd, fmaf(xv.x, wi, bh)));
        hv = tanh_hw(fmaf(hv, wd, fmaf(xv.y, wi, bh)));
        hv = tanh_hw(fmaf(hv, wd, fmaf(xv.z, wi, bh)));
        hv = tanh_hw(fmaf(hv, wd, fmaf(xv.w, wi, bh)));
    }

    hs[h] = hv;
    __syncthreads();

    // Epilogue: 160 threads produce 16-wide partials; 10 threads reduce.
    if (h < RC * 16) {
        const int c   = h >> 4;
        const int seg = h & 15;
        const float* wrow = W_hp + c * RH + seg * 16;
        const float* hrow = hs + seg * 16;
        float acc = 0.0f;
        #pragma unroll
        for (int j = 0; j < 16; j++)
            acc = fmaf(hrow[j], wrow[j], acc);
        psum[c][seg] = acc;
    }
    __syncthreads();

    if (h < RC) {
        float acc = b_o[h];
        #pragma unroll
        for (int s = 0; s < 16; s++)
            acc += psum[h][s];
        out[b * RC + h] = acc;
    }
}

extern "C" void kernel_launch(void* const* d_in, const int* in_sizes, int n_in,
                              void* d_out, int out_size)
{
    const float* x    = (const float*)d_in[0];
    const float* W_hx = (const float*)d_in[1];
    const float* W_hh = (const float*)d_in[2];
    const float* b_h  = (const float*)d_in[3];
    const float* W_hp = (const float*)d_in[4];
    const float* b_o  = (const float*)d_in[5];
    float* out = (float*)d_out;

    vanilla_rnn_kernel<<<RB, RH>>>(x, W_hx, W_hh, b_h, W_hp, b_o, out);
}